// round 1
// baseline (speedup 1.0000x reference)
#include <cuda_runtime.h>
#include <cuda_bf16.h>

// ChannelPruner: out[b,o,h,w] = sum_c w[o,c] * x[b,c,h,w]
// x: (32, 256, 56, 56) fp32, w: (256, 256, 1, 1) fp32.
// Generic sparse-row formulation: per output channel o, compact the nonzeros
// of row w[o,:] (deterministically) and accumulate only those input planes.
// For the pruned-identity weight this is a copy-or-zero -> pure memory bound.

#define N_CH   256
#define HW4    784          // 56*56/4 float4 per plane
#define NBATCH 32

__global__ __launch_bounds__(256, 8)
void channel_pruner_kernel(const float4* __restrict__ X,
                           const float4* __restrict__ W,   // w as float4: row o = W[o*64 .. o*64+63]
                           float4* __restrict__ O)
{
    const int o = blockIdx.y;     // output channel
    const int b = blockIdx.z;     // batch
    const int tid = threadIdx.x;  // 256 threads

    __shared__ int   s_cnt[64];
    __shared__ int   s_off[64];
    __shared__ int   s_nnz;
    __shared__ int   s_c[N_CH];
    __shared__ float s_v[N_CH];

    // --- Phase 1: cooperative scan of w row o (64 float4 = 256 floats) ---
    float4 w4;
    int myCnt = 0;
    if (tid < 64) {
        w4 = __ldg(&W[o * 64 + tid]);
        myCnt = (w4.x != 0.0f) + (w4.y != 0.0f) + (w4.z != 0.0f) + (w4.w != 0.0f);
        s_cnt[tid] = myCnt;
    }
    __syncthreads();

    // Deterministic serial exclusive scan by thread 0 (64 adds; negligible)
    if (tid == 0) {
        int run = 0;
        #pragma unroll
        for (int i = 0; i < 64; i++) {
            s_off[i] = run;
            run += s_cnt[i];
        }
        s_nnz = run;
    }
    __syncthreads();

    if (tid < 64 && myCnt > 0) {
        int p = s_off[tid];
        int cbase = tid * 4;
        if (w4.x != 0.0f) { s_c[p] = cbase + 0; s_v[p] = w4.x; p++; }
        if (w4.y != 0.0f) { s_c[p] = cbase + 1; s_v[p] = w4.y; p++; }
        if (w4.z != 0.0f) { s_c[p] = cbase + 2; s_v[p] = w4.z; p++; }
        if (w4.w != 0.0f) { s_c[p] = cbase + 3; s_v[p] = w4.w; p++; }
    }
    __syncthreads();

    const int nnz = s_nnz;
    const float4* __restrict__ Xb = X + (size_t)b * N_CH * HW4;
    float4* __restrict__ Ob = O + ((size_t)b * N_CH + o) * HW4;

    // --- Phase 2: stream the plane. Common cases specialized for MLP. ---
    if (nnz == 0) {
        const float4 z = make_float4(0.f, 0.f, 0.f, 0.f);
        #pragma unroll
        for (int s = tid; s < HW4; s += 256) Ob[s] = z;
    } else if (nnz == 1) {
        const float v = s_v[0];
        const float4* __restrict__ Xc = Xb + (size_t)s_c[0] * HW4;
        // 784 = 3*256 + 16: batch the three full strides for load-level parallelism
        float4 a0 = __ldg(&Xc[tid]);
        float4 a1 = __ldg(&Xc[tid + 256]);
        float4 a2 = __ldg(&Xc[tid + 512]);
        float4 a3;
        if (tid < HW4 - 768) a3 = __ldg(&Xc[tid + 768]);
        a0.x *= v; a0.y *= v; a0.z *= v; a0.w *= v;
        a1.x *= v; a1.y *= v; a1.z *= v; a1.w *= v;
        a2.x *= v; a2.y *= v; a2.z *= v; a2.w *= v;
        Ob[tid]       = a0;
        Ob[tid + 256] = a1;
        Ob[tid + 512] = a2;
        if (tid < HW4 - 768) {
            a3.x *= v; a3.y *= v; a3.z *= v; a3.w *= v;
            Ob[tid + 768] = a3;
        }
    } else {
        for (int s = tid; s < HW4; s += 256) {
            float4 acc = make_float4(0.f, 0.f, 0.f, 0.f);
            for (int k = 0; k < nnz; k++) {
                const float v = s_v[k];
                const float4 xv = __ldg(&Xb[(size_t)s_c[k] * HW4 + s]);
                acc.x += v * xv.x;
                acc.y += v * xv.y;
                acc.z += v * xv.z;
                acc.w += v * xv.w;
            }
            Ob[s] = acc;
        }
    }
}

extern "C" void kernel_launch(void* const* d_in, const int* in_sizes, int n_in,
                              void* d_out, int out_size)
{
    const float4* X = (const float4*)d_in[0];   // x: 32*256*56*56 fp32
    const float4* W = (const float4*)d_in[1];   // conv_weights: 256*256*1*1 fp32
    float4* O = (float4*)d_out;

    dim3 grid(1, N_CH, NBATCH);   // 8192 blocks: one per (b, o) plane
    dim3 block(256);
    channel_pruner_kernel<<<grid, block>>>(X, W, O);
}